// round 1
// baseline (speedup 1.0000x reference)
#include <cuda_runtime.h>

#define NW 10
#define DIMQ 1024
#define NB 4
#define NTHREADS 256
#define EPT 4   // elements per thread (1024/256)

__device__ __forceinline__ float diag_angle(const float* __restrict__ th, int s) {
    // exp(-0.5i * theta . zval), zval = 1-2*bit  =>  angle = sum th[w]*(bit-0.5)
    float a = 0.f;
#pragma unroll
    for (int w = 0; w < NW; w++) {
        float bb = (float)((s >> (9 - w)) & 1);
        a = fmaf(th[w], bb - 0.5f, a);
    }
    return a;
}

__global__ __launch_bounds__(NTHREADS, 8)
void quantum_layer_kernel(const float* __restrict__ x,
                          const float* __restrict__ params,
                          float* __restrict__ out)
{
    __shared__ float sre[DIMQ];
    __shared__ float sim[DIMQ];
    __shared__ int   sperm[DIMQ];
    __shared__ float spar[NB * 6 * NW];
    __shared__ float sx[NW];
    __shared__ float scs[NB * 2 * NW * 2];   // 8 RY layers x 10 wires x (cos,sin)
    __shared__ float wred[8 * NW];

    const int tid = threadIdx.x;
    const int b   = blockIdx.x;

    // ---- load params & x row ----
    for (int i = tid; i < NB * 6 * NW; i += NTHREADS) spar[i] = params[i];
    if (tid < NW) sx[tid] = x[b * NW + tid];

    // ---- ring-CNOT permutation table: P = g_(0,1) o g_(1,2) o ... o g_(9,0) ----
#pragma unroll
    for (int j = 0; j < EPT; j++) {
        int s = tid + j * NTHREADS;
        int idx = s;
#pragma unroll
        for (int q = 9; q >= 0; --q) {
            int c = q, t = (q + 1) % NW;
            int bit = (idx >> (9 - c)) & 1;
            idx ^= bit << (9 - t);
        }
        sperm[s] = idx;
    }

    // ---- init state: |0>, with block-0 rz(p0) phase folded in ----
#pragma unroll
    for (int j = 0; j < EPT; j++) {
        int s = tid + j * NTHREADS;
        sre[s] = 0.f;
        sim[s] = 0.f;
    }
    __syncthreads();   // spar ready

    // ---- precompute RY half-angle cos/sin tables (8 layers x 10 wires) ----
    if (tid < 80) {
        int k = tid / 20, rest = tid % 20, ry = rest / 10, w = rest % 10;
        float th = 0.5f * spar[(k * 6 + (ry ? 4 : 1)) * NW + w];
        scs[tid * 2]     = cosf(th);
        scs[tid * 2 + 1] = sinf(th);
    }
    if (tid == 0) {
        float a = 0.f;
#pragma unroll
        for (int w = 0; w < NW; w++) a -= 0.5f * spar[w];   // p0 angle at s=0 (all bits 0)
        sre[0] = cosf(a);
        sim[0] = sinf(a);
    }
    __syncthreads();

    // ============================ circuit ============================
    for (int k = 0; k < NB; k++) {
        const float* pk = spar + k * 6 * NW;

        // ---- RY layer (p1) and later (p4): 10 wire sweeps each ----
#pragma unroll
        for (int ry = 0; ry < 2; ry++) {
            const float* cs = scs + k * 40 + ry * 20;
#pragma unroll
            for (int w = 0; w < NW; w++) {
                float cw = cs[2 * w], sw = cs[2 * w + 1];
                int right = 1 << (9 - w);
                int mask  = right - 1;
#pragma unroll
                for (int pp = 0; pp < 2; pp++) {
                    int p  = tid + pp * NTHREADS;
                    int s0 = ((p & ~mask) << 1) | (p & mask);
                    int s1 = s0 + right;
                    float a0 = sre[s0], a1 = sre[s1];
                    float b0 = sim[s0], b1 = sim[s1];
                    sre[s0] = cw * a0 - sw * a1;
                    sre[s1] = sw * a0 + cw * a1;
                    sim[s0] = cw * b0 - sw * b1;
                    sim[s1] = sw * b0 + cw * b1;
                }
                __syncthreads();
            }

            // ---- fused pass: perm + diagonals ----
            float rr[EPT], ri[EPT];
#pragma unroll
            for (int j = 0; j < EPT; j++) {
                int s  = tid + j * NTHREADS;
                int ps = sperm[s];
                float ang;
                if (ry == 0) {
                    // rz(p2); perm; rz(p3)
                    ang = diag_angle(pk + 2 * NW, ps) + diag_angle(pk + 3 * NW, s);
                } else {
                    // rz(p5); perm; [enc(x); rz(p0_next)] if not last block
                    ang = diag_angle(pk + 5 * NW, ps);
                    if (k < NB - 1) {
                        ang += diag_angle(sx, s);
                        ang += diag_angle(spar + (k + 1) * 6 * NW, s);
                    }
                }
                float sn, cn;
                __sincosf(ang, &sn, &cn);
                float orr = sre[ps], oii = sim[ps];
                rr[j] = orr * cn - oii * sn;
                ri[j] = orr * sn + oii * cn;
            }
            __syncthreads();
#pragma unroll
            for (int j = 0; j < EPT; j++) {
                int s = tid + j * NTHREADS;
                sre[s] = rr[j];
                sim[s] = ri[j];
            }
            __syncthreads();
        }
    }

    // ============================ measurement ============================
    // out[b][w] = sum_s (re^2+im^2) * (1 - 2*bit_w(s))
    float acc[NW];
#pragma unroll
    for (int w = 0; w < NW; w++) acc[w] = 0.f;

#pragma unroll
    for (int j = 0; j < EPT; j++) {
        int s = tid + j * NTHREADS;
        float pr = sre[s] * sre[s] + sim[s] * sim[s];
#pragma unroll
        for (int w = 0; w < NW; w++) {
            acc[w] += ((s >> (9 - w)) & 1) ? -pr : pr;
        }
    }

    // warp reduce
#pragma unroll
    for (int off = 16; off > 0; off >>= 1) {
#pragma unroll
        for (int w = 0; w < NW; w++)
            acc[w] += __shfl_down_sync(0xFFFFFFFFu, acc[w], off);
    }
    int warp = tid >> 5, lane = tid & 31;
    if (lane == 0) {
#pragma unroll
        for (int w = 0; w < NW; w++) wred[warp * NW + w] = acc[w];
    }
    __syncthreads();
    if (tid < NW) {
        float t = 0.f;
#pragma unroll
        for (int wp = 0; wp < 8; wp++) t += wred[wp * NW + tid];
        out[b * NW + tid] = t;
    }
}

extern "C" void kernel_launch(void* const* d_in, const int* in_sizes, int n_in,
                              void* d_out, int out_size)
{
    const float* x      = (const float*)d_in[0];   // (2048, 10)
    const float* params = (const float*)d_in[1];   // (4, 6, 10)
    float* out          = (float*)d_out;           // (1, 2048, 10)
    quantum_layer_kernel<<<2048, NTHREADS>>>(x, params, out);
}

// round 10
// speedup vs baseline: 2.6851x; 2.6851x over previous
#include <cuda_runtime.h>

#define NW 10
typedef unsigned long long u64;

// Precomputed phase tables: [pass = k*2+ry][ j*32 + lane ]  (transposed for coalescing)
__device__ float2 g_tab[8][1024];

// ---------- packed f32x2 helpers ----------
__device__ __forceinline__ u64 pk2(float x, float y) {
    u64 r; asm("mov.b64 %0, {%1,%2};" : "=l"(r) : "f"(x), "f"(y)); return r;
}
__device__ __forceinline__ void upk2(u64 v, float &x, float &y) {
    asm("mov.b64 {%0,%1}, %2;" : "=f"(x), "=f"(y) : "l"(v));
}
__device__ __forceinline__ u64 pfma(u64 a, u64 b, u64 c) {   // a*b + c (elementwise)
    u64 d; asm("fma.rn.f32x2 %0, %1, %2, %3;" : "=l"(d) : "l"(a), "l"(b), "l"(c)); return d;
}
__device__ __forceinline__ u64 pmul(u64 a, u64 b) {
    u64 d; asm("mul.rn.f32x2 %0, %1, %2;" : "=l"(d) : "l"(a), "l"(b)); return d;
}

// ---------- ring-CNOT permutation: GF(2)-linear, compile-time basis images ----------
// image of basis bit p (bit 0 = LSB of the 10-bit state index)
__host__ __device__ constexpr int PBf(int p) {
    return p==0?769 : p==1?3 : p==2?6 : p==3?12 : p==4?24
         : p==5?48 : p==6?96 : p==7?192 : p==8?384 : 768;
}
__host__ __device__ constexpr int permImgC(int s) {
    int r = 0;
    for (int p = 0; p < 10; p++) r ^= ((s >> p) & 1) * PBf(p);
    return r;
}
// bank-conflict-free swizzle (invertible on both write & gather lane patterns)
__host__ __device__ constexpr int physC(int s) {
    return (s & ~31) | ((s ^ (s >> 5) ^ (s >> 9)) & 31);
}

// ---------- table precompute kernel (params-only phases, incl. perm-composed) ----------
__global__ void precompute_tables(const float* __restrict__ params) {
    int p = blockIdx.x;          // 0..7
    int s = threadIdx.x;         // 0..1023
    int k = p >> 1, ry = p & 1;

    // perm image of s (runtime chain, matches reference composition)
    int idx = s;
    for (int q = 9; q >= 0; --q) {
        int c = q, t = (q + 1) % NW;
        int bit = (idx >> (9 - c)) & 1;
        idx ^= bit << (9 - t);
    }

    const float* thA = params + (k * 6 + (ry ? 5 : 2)) * NW;  // applied at perm-image
    float ang = 0.f;
#pragma unroll
    for (int w = 0; w < NW; w++)
        ang += thA[w] * ((float)((idx >> (9 - w)) & 1) - 0.5f);

    if (ry == 0) {
        const float* th3 = params + (k * 6 + 3) * NW;
#pragma unroll
        for (int w = 0; w < NW; w++)
            ang += th3[w] * ((float)((s >> (9 - w)) & 1) - 0.5f);
    } else if (k < 3) {
        const float* th0 = params + ((k + 1) * 6) * NW;       // next block's leading rz
#pragma unroll
        for (int w = 0; w < NW; w++)
            ang += th0[w] * ((float)((s >> (9 - w)) & 1) - 0.5f);
    }
    float sn, cn;
    sincosf(ang, &sn, &cn);
    g_tab[p][(s & 31) * 32 + (s >> 5)] = make_float2(cn, sn);
}

// ---------- main kernel: 1 warp per batch element, state in registers ----------
__global__ __launch_bounds__(32, 16)
void quantum_warp_kernel(const float* __restrict__ x,
                         const float* __restrict__ params,
                         float* __restrict__ out)
{
    __shared__ u64    sbuf[1024];   // perm-pass exchange buffer (swizzled)
    __shared__ float2 scs[80];      // RY (cos,sin) per [k*2+ry][wire]

    const int lane = threadIdx.x;
    const int b    = blockIdx.x;

    // RY coefficient tables (half angles)
    for (int i = lane; i < 80; i += 32) {
        int k = i / 20, r = (i / 10) % 2, w = i % 10;
        float th = 0.5f * params[(k * 6 + (r ? 4 : 1)) * NW + w];
        scs[i] = make_float2(cosf(th), sinf(th));
    }

    // x row: high (lane-bit) part + half-values for low-bit (j) part
    float xv[NW];
#pragma unroll
    for (int w = 0; w < NW; w++) xv[w] = x[b * NW + w];
    float xhi = 0.f;
#pragma unroll
    for (int w = 0; w < 5; w++)
        xhi += xv[w] * ((float)((lane >> (4 - w)) & 1) - 0.5f);
    float h0 = 0.5f * xv[9], h1 = 0.5f * xv[8], h2 = 0.5f * xv[7],
          h3 = 0.5f * xv[6], h4 = 0.5f * xv[5];

    // per-thread perm/gather bases (lane bits 0..4 map to state bits 5..9)
    int B = 0;
#pragma unroll
    for (int p = 0; p < 5; p++) if ((lane >> p) & 1) B ^= PBf(p + 5);
    const int physB = physC(B);
    const int wbase = lane * 32;
    const int lx    = (lane ^ (lane >> 4)) & 31;   // write swizzle

    // ---- init: |0> with block-0 rz(p0) folded in ----
    u64 st[32];
#pragma unroll
    for (int j = 0; j < 32; j++) st[j] = 0ull;
    if (lane == 0) {
        float a = 0.f;
#pragma unroll
        for (int w = 0; w < NW; w++) a -= 0.5f * params[w];
        float sn, cn; sincosf(a, &sn, &cn);
        st[0] = pk2(cn, sn);
    }
    __syncwarp();   // scs ready

    // ============================ circuit ============================
#pragma unroll 1
    for (int k = 0; k < 4; k++) {
#pragma unroll 1
        for (int ry = 0; ry < 2; ry++) {
            const float2* cs = scs + (k * 2 + ry) * NW;

            // ---- RY: lane wires 0..4 (shfl butterflies) ----
#pragma unroll
            for (int w = 0; w < 5; w++) {
                float2 c = cs[w];
                u64 c2   = pk2(c.x, c.x);
                u64 coef = ((lane >> (4 - w)) & 1) ? pk2(c.y, c.y) : pk2(-c.y, -c.y);
                const int m = 1 << (4 - w);
#pragma unroll
                for (int j = 0; j < 32; j++) {
                    u64 pv = __shfl_xor_sync(0xFFFFFFFFu, st[j], m);
                    st[j] = pfma(c2, st[j], pmul(coef, pv));
                }
            }
            // ---- RY: register wires 5..9 (in-thread butterflies) ----
#pragma unroll
            for (int w = 5; w < 10; w++) {
                float2 c = cs[w];
                u64 c2 = pk2(c.x, c.x), s2 = pk2(c.y, c.y), ns2 = pk2(-c.y, -c.y);
                const int m = 1 << (9 - w);
#pragma unroll
                for (int j = 0; j < 32; j++) {
                    if (!(j & m)) {
                        u64 a0 = st[j], a1 = st[j | m];
                        st[j]     = pfma(c2, a0, pmul(ns2, a1));
                        st[j | m] = pfma(s2, a0, pmul(c2, a1));
                    }
                }
            }

            // ---- fused perm + diagonal pass ----
            __syncwarp();
#pragma unroll
            for (int j = 0; j < 32; j++) sbuf[wbase + (j ^ lx)] = st[j];
            __syncwarp();

            const float2* __restrict__ tab = g_tab[k * 2 + ry];
            const bool doEnc = (ry == 1) && (k < 3);

            if (doEnc) {
#pragma unroll
                for (int j = 0; j < 32; j++) {
                    u64 ov = sbuf[physB ^ physC(permImgC(j))];
                    float ox, oy; upk2(ov, ox, oy);
                    float2 t = tab[j * 32 + lane];
                    float rr = ox * t.x - oy * t.y;
                    float ii = ox * t.y + oy * t.x;
                    float ang = xhi
                        + ((j & 1)  ? h0 : -h0) + ((j & 2)  ? h1 : -h1)
                        + ((j & 4)  ? h2 : -h2) + ((j & 8)  ? h3 : -h3)
                        + ((j & 16) ? h4 : -h4);
                    float se, ce; __sincosf(ang, &se, &ce);
                    st[j] = pk2(rr * ce - ii * se, rr * se + ii * ce);
                }
            } else {
#pragma unroll
                for (int j = 0; j < 32; j++) {
                    u64 ov = sbuf[physB ^ physC(permImgC(j))];
                    float ox, oy; upk2(ov, ox, oy);
                    float2 t = tab[j * 32 + lane];
                    st[j] = pk2(ox * t.x - oy * t.y, ox * t.y + oy * t.x);
                }
            }
        }
    }

    // ============================ measurement ============================
    float a59[5] = {0.f, 0.f, 0.f, 0.f, 0.f};   // wires 9..5 (index p: wire 9-p)
    float pt = 0.f;
#pragma unroll
    for (int j = 0; j < 32; j++) {
        float re, im; upk2(st[j], re, im);
        float pr = fmaf(re, re, im * im);
        pt += pr;
#pragma unroll
        for (int p = 0; p < 5; p++)
            a59[p] += ((j >> p) & 1) ? -pr : pr;
    }
    float acc[NW];
#pragma unroll
    for (int w = 0; w < 5; w++)
        acc[w] = ((lane >> (4 - w)) & 1) ? -pt : pt;
#pragma unroll
    for (int w = 5; w < 10; w++)
        acc[w] = a59[9 - w];

#pragma unroll
    for (int off = 16; off > 0; off >>= 1) {
#pragma unroll
        for (int w = 0; w < NW; w++)
            acc[w] += __shfl_xor_sync(0xFFFFFFFFu, acc[w], off);
    }
    if (lane == 0) {
#pragma unroll
        for (int w = 0; w < NW; w++) out[b * NW + w] = acc[w];
    }
}

extern "C" void kernel_launch(void* const* d_in, const int* in_sizes, int n_in,
                              void* d_out, int out_size)
{
    const float* x      = (const float*)d_in[0];   // (2048, 10)
    const float* params = (const float*)d_in[1];   // (4, 6, 10)
    float* out          = (float*)d_out;           // (1, 2048, 10)
    precompute_tables<<<8, 1024>>>(params);
    quantum_warp_kernel<<<2048, 32>>>(x, params, out);
}

// round 11
// speedup vs baseline: 2.6895x; 1.0017x over previous
#include <cuda_runtime.h>

#define NW 10
typedef unsigned long long u64;

// Precomputed phase tables: [pass = k*2+ry][ s ]  (natural order; lanes = low bits)
__device__ float2 g_tab[8][1024];

// ---------- packed f32x2 helpers ----------
__device__ __forceinline__ u64 pk2(float x, float y) {
    u64 r; asm("mov.b64 %0, {%1,%2};" : "=l"(r) : "f"(x), "f"(y)); return r;
}
__device__ __forceinline__ void upk2(u64 v, float &x, float &y) {
    asm("mov.b64 {%0,%1}, %2;" : "=f"(x), "=f"(y) : "l"(v));
}
__device__ __forceinline__ u64 pfma(u64 a, u64 b, u64 c) {   // a*b + c (elementwise)
    u64 d; asm("fma.rn.f32x2 %0, %1, %2, %3;" : "=l"(d) : "l"(a), "l"(b), "l"(c)); return d;
}
__device__ __forceinline__ u64 pmul(u64 a, u64 b) {
    u64 d; asm("mul.rn.f32x2 %0, %1, %2;" : "=l"(d) : "l"(a), "l"(b)); return d;
}

// ---------- ring-CNOT permutation: GF(2)-linear basis images (bit 0 = LSB) ----------
__host__ __device__ constexpr int PBf(int p) {
    return p==0?769 : p==1?3 : p==2?6 : p==3?12 : p==4?24
         : p==5?48 : p==6?96 : p==7?192 : p==8?384 : 768;
}
// perm image of the j-part (state bits 9..6 = j bits 3..0)
__host__ __device__ constexpr int permJ(int j) {
    return ((j&1)?PBf(6):0) ^ ((j&2)?PBf(7):0) ^ ((j&4)?PBf(8):0) ^ ((j&8)?PBf(9):0);
}

// ---------- table precompute kernel (params-only phases, incl. perm-composed) ----------
__global__ void precompute_tables(const float* __restrict__ params) {
    int p = blockIdx.x;          // 0..7
    int s = threadIdx.x;         // 0..1023
    int k = p >> 1, ry = p & 1;

    // perm image of s (runtime chain, matches reference composition)
    int idx = s;
    for (int q = 9; q >= 0; --q) {
        int c = q, t = (q + 1) % NW;
        int bit = (idx >> (9 - c)) & 1;
        idx ^= bit << (9 - t);
    }

    const float* thA = params + (k * 6 + (ry ? 5 : 2)) * NW;  // applied at perm-image
    float ang = 0.f;
#pragma unroll
    for (int w = 0; w < NW; w++)
        ang += thA[w] * ((float)((idx >> (9 - w)) & 1) - 0.5f);

    if (ry == 0) {
        const float* th3 = params + (k * 6 + 3) * NW;
#pragma unroll
        for (int w = 0; w < NW; w++)
            ang += th3[w] * ((float)((s >> (9 - w)) & 1) - 0.5f);
    } else if (k < 3) {
        const float* th0 = params + ((k + 1) * 6) * NW;       // next block's leading rz
#pragma unroll
        for (int w = 0; w < NW; w++)
            ang += th0[w] * ((float)((s >> (9 - w)) & 1) - 0.5f);
    }
    float sn, cn;
    sincosf(ang, &sn, &cn);
    g_tab[p][s] = make_float2(cn, sn);
}

// ---------- main kernel: 2 warps per batch element, 16 amps per lane ----------
// state index s = (j<<6) | (wb<<5) | lane
//   wires 0..3  <-> j bits 3..0      (register butterflies)
//   wire  4     <-> wb               (fused into perm pass)
//   wires 5..9  <-> lane bits 4..0   (shfl butterflies)
__global__ __launch_bounds__(64, 12)
void quantum_warp2_kernel(const float* __restrict__ x,
                          const float* __restrict__ params,
                          float* __restrict__ out)
{
    __shared__ u64    sbuf[1024];   // exchange buffer
    __shared__ float2 scs[80];      // RY (cos,sin) per [k*2+ry][wire]
    __shared__ float  wred[2 * NW];

    const int tid  = threadIdx.x;
    const int lane = tid & 31;
    const int wb   = tid >> 5;
    const int b    = blockIdx.x;

    // RY coefficient tables (half angles)
    for (int i = tid; i < 80; i += 64) {
        int k = i / 20, r = (i / 10) % 2, w = i % 10;
        float th = 0.5f * params[(k * 6 + (r ? 4 : 1)) * NW + w];
        scs[i] = make_float2(cosf(th), sinf(th));
    }

    // encoding angle: lane+warp part (wires 4..9) + half-values for j part (wires 0..3)
    float xv[NW];
#pragma unroll
    for (int w = 0; w < NW; w++) xv[w] = x[b * NW + w];
    float xbase = xv[4] * ((float)wb - 0.5f);
#pragma unroll
    for (int w = 5; w < NW; w++)
        xbase += xv[w] * ((float)((lane >> (9 - w)) & 1) - 0.5f);
    const float h0 = 0.5f * xv[0], h1 = 0.5f * xv[1],
                h2 = 0.5f * xv[2], h3 = 0.5f * xv[3];

    // perm image of the (wb,lane) part: state bits 5..0
    int B = 0;
#pragma unroll
    for (int p = 0; p < 5; p++) if ((lane >> p) & 1) B ^= PBf(p);
    if (wb) B ^= PBf(5);

    // ---- init: |0> with block-0 rz(p0) folded in ----
    u64 st[16];
#pragma unroll
    for (int j = 0; j < 16; j++) st[j] = 0ull;
    if (tid == 0) {   // s = 0 lives at wb=0, lane=0, j=0
        float a = 0.f;
#pragma unroll
        for (int w = 0; w < NW; w++) a -= 0.5f * params[w];
        float sn, cn; sincosf(a, &sn, &cn);
        st[0] = pk2(cn, sn);
    }
    __syncthreads();   // scs ready

    // ============================ circuit ============================
#pragma unroll 1
    for (int k = 0; k < 4; k++) {
#pragma unroll 1
        for (int ry = 0; ry < 2; ry++) {
            const float2* cs = scs + (k * 2 + ry) * NW;

            // ---- RY register wires 0..3 (j-bit butterflies) ----
#pragma unroll
            for (int w = 0; w < 4; w++) {
                float2 c = cs[w];
                u64 c2 = pk2(c.x, c.x), s2 = pk2(c.y, c.y), ns2 = pk2(-c.y, -c.y);
                const int m = 1 << (3 - w);
#pragma unroll
                for (int j = 0; j < 16; j++) {
                    if (!(j & m)) {
                        u64 a0 = st[j], a1 = st[j | m];
                        st[j]     = pfma(c2, a0, pmul(ns2, a1));
                        st[j | m] = pfma(s2, a0, pmul(c2, a1));
                    }
                }
            }

            // ---- RY lane wires 5..9 (shfl butterflies) ----
#pragma unroll
            for (int w = 5; w < 10; w++) {
                float2 c = cs[w];
                u64 c2   = pk2(c.x, c.x);
                u64 coef = ((lane >> (9 - w)) & 1) ? pk2(c.y, c.y) : pk2(-c.y, -c.y);
                const int m = 1 << (9 - w);
#pragma unroll
                for (int j = 0; j < 16; j++) {
                    u64 pv = __shfl_xor_sync(0xFFFFFFFFu, st[j], m);
                    st[j] = pfma(c2, st[j], pmul(coef, pv));
                }
            }

            // ---- fused: wire-4 butterfly + perm + diagonal pass ----
            float2 c4 = cs[4];
            u64 c42 = pk2(c4.x, c4.x);
            u64 s4p = pk2(c4.y, c4.y), s4n = pk2(-c4.y, -c4.y);

            __syncthreads();   // previous pass's reads done
#pragma unroll
            for (int j = 0; j < 16; j++)
                sbuf[(j << 6) | (wb << 5) | lane] = st[j];
            __syncthreads();

            const float2* __restrict__ tab = g_tab[k * 2 + ry];
            const bool doEnc = (ry == 1) && (k < 3);

#pragma unroll
            for (int j = 0; j < 16; j++) {
                const int a1 = B ^ permJ(j);        // perm(s), s = (j<<6)|(wb<<5)|lane
                u64 own = sbuf[a1];
                u64 par = sbuf[a1 ^ 32];
                // wire-4 butterfly applied at source index a1 (bit 5 selects sign)
                u64 v = pfma(c42, own, pmul((a1 & 32) ? s4p : s4n, par));
                float ox, oy; upk2(v, ox, oy);
                float2 t = tab[(j << 6) | (wb << 5) | lane];
                float rr = ox * t.x - oy * t.y;
                float ii = ox * t.y + oy * t.x;
                if (doEnc) {
                    float ang = xbase
                        + ((j & 8) ? h0 : -h0) + ((j & 4) ? h1 : -h1)
                        + ((j & 2) ? h2 : -h2) + ((j & 1) ? h3 : -h3);
                    float se, ce; __sincosf(ang, &se, &ce);
                    st[j] = pk2(rr * ce - ii * se, rr * se + ii * ce);
                } else {
                    st[j] = pk2(rr, ii);
                }
            }
        }
    }

    // ============================ measurement ============================
    float a03[4] = {0.f, 0.f, 0.f, 0.f};
    float pt = 0.f;
#pragma unroll
    for (int j = 0; j < 16; j++) {
        float re, im; upk2(st[j], re, im);
        float pr = fmaf(re, re, im * im);
        pt += pr;
        a03[0] += (j & 8) ? -pr : pr;   // wire 0 <-> j bit 3
        a03[1] += (j & 4) ? -pr : pr;
        a03[2] += (j & 2) ? -pr : pr;
        a03[3] += (j & 1) ? -pr : pr;
    }
    float acc[NW];
#pragma unroll
    for (int w = 0; w < 4; w++) acc[w] = a03[w];
    acc[4] = wb ? -pt : pt;
#pragma unroll
    for (int w = 5; w < NW; w++)
        acc[w] = ((lane >> (9 - w)) & 1) ? -pt : pt;

#pragma unroll
    for (int off = 16; off > 0; off >>= 1) {
#pragma unroll
        for (int w = 0; w < NW; w++)
            acc[w] += __shfl_xor_sync(0xFFFFFFFFu, acc[w], off);
    }
    if (lane == 0) {
#pragma unroll
        for (int w = 0; w < NW; w++) wred[wb * NW + w] = acc[w];
    }
    __syncthreads();
    if (tid < NW) out[b * NW + tid] = wred[tid] + wred[NW + tid];
}

extern "C" void kernel_launch(void* const* d_in, const int* in_sizes, int n_in,
                              void* d_out, int out_size)
{
    const float* x      = (const float*)d_in[0];   // (2048, 10)
    const float* params = (const float*)d_in[1];   // (4, 6, 10)
    float* out          = (float*)d_out;           // (1, 2048, 10)
    precompute_tables<<<8, 1024>>>(params);
    quantum_warp2_kernel<<<2048, 64>>>(x, params, out);
}